// round 3
// baseline (speedup 1.0000x reference)
#include <cuda_runtime.h>
#include <cuda_bf16.h>
#include <math.h>

#define N_NODES  50000
#define N_EDGES  1600000
#define IN_CH    64
#define HID      16
#define NCLS     10
#define HID2P    12

// ---------------- device scratch ----------------
__device__ __align__(16) float g_y1  [N_NODES * HID];    // x @ w_rel1
__device__ __align__(16) float g_r1  [N_NODES * HID];    // x @ w_root1
__device__ __align__(16) float g_agg1[N_NODES * HID];    // segment_sum(y1)
__device__ __align__(16) float g_y2  [N_NODES * HID2P];  // h @ w_rel2 (padded)
__device__ __align__(16) float g_r2  [N_NODES * HID2P];  // h @ w_root2
__device__ __align__(16) float g_agg2[N_NODES * HID2P];  // segment_sum(y2)
__device__ int g_deg[N_NODES];          // in-degree histogram
__device__ int g_row[N_NODES + 1];      // CSR row offsets
__device__ int g_cur[N_NODES];          // fill cursors
__device__ int g_adj[N_EDGES];          // src ids grouped by dst
__device__ int g_is64;                  // edge buffer dtype flag

// ---------------- kernels ----------------

// Detect edge index dtype: int64 values < 2^31 -> all odd 32-bit words zero.
__global__ void k_detect(const int* __restrict__ ei32) {
    __shared__ int s_or;
    if (threadIdx.x == 0) s_or = 0;
    __syncthreads();
    int v = 0;
    for (int i = threadIdx.x; i < 1024; i += blockDim.x)
        v |= ei32[2 * i + 1];
    if (v) atomicOr(&s_or, 1);
    __syncthreads();
    if (threadIdx.x == 0) g_is64 = (s_or == 0) ? 1 : 0;
}

__global__ void k_zero() {
    for (int i = blockIdx.x * blockDim.x + threadIdx.x; i < N_NODES;
         i += gridDim.x * blockDim.x)
        g_deg[i] = 0;
}

// Histogram of dst
__global__ __launch_bounds__(256) void k_hist(const void* __restrict__ ei) {
    const bool is64 = (g_is64 != 0);
    int e = blockIdx.x * 256 + threadIdx.x;
    if (e >= N_EDGES) return;
    int d = is64 ? (int)((const long long*)ei)[N_EDGES + e]
                 : ((const int*)ei)[N_EDGES + e];
    atomicAdd(&g_deg[d], 1);
}

// Single-block exclusive scan of degrees -> row offsets + fill cursors
__global__ __launch_bounds__(1024) void k_scan() {
    __shared__ int s[1024];
    const int t = threadIdx.x;
    const int CH = (N_NODES + 1023) / 1024;   // 49
    int beg = t * CH;
    int end = beg + CH; if (end > N_NODES) end = N_NODES;

    int sum = 0;
    for (int i = beg; i < end; i++) sum += g_deg[i];
    s[t] = sum;
    __syncthreads();
    // Hillis-Steele inclusive scan
    for (int off = 1; off < 1024; off <<= 1) {
        int v = (t >= off) ? s[t - off] : 0;
        __syncthreads();
        s[t] += v;
        __syncthreads();
    }
    int base = (t == 0) ? 0 : s[t - 1];
    for (int i = beg; i < end; i++) {
        g_row[i] = base;
        g_cur[i] = base;
        base += g_deg[i];
    }
    if (t == 0) g_row[N_NODES] = N_EDGES;
}

// Fill adjacency: adj grouped by dst, holding src ids
__global__ __launch_bounds__(256) void k_fill(const void* __restrict__ ei) {
    const bool is64 = (g_is64 != 0);
    int e = blockIdx.x * 256 + threadIdx.x;
    if (e >= N_EDGES) return;
    int s, d;
    if (is64) {
        const long long* p = (const long long*)ei;
        s = (int)p[e];
        d = (int)p[N_EDGES + e];
    } else {
        const int* p = (const int*)ei;
        s = p[e];
        d = p[N_EDGES + e];
    }
    int pos = atomicAdd(&g_cur[d], 1);
    g_adj[pos] = s;
}

// Layer-1 projections, 4-way split: thread = node*4 + part
// part: 0 -> rel cols 0-7, 1 -> rel 8-15, 2 -> root 0-7, 3 -> root 8-15
__global__ __launch_bounds__(256) void k_lin1(const float* __restrict__ x,
                                              const float* __restrict__ w_rel,
                                              const float* __restrict__ w_root) {
    __shared__ float sw[IN_CH * HID];
    __shared__ float su[IN_CH * HID];
    for (int i = threadIdx.x; i < IN_CH * HID; i += 256) {
        sw[i] = w_rel[i];
        su[i] = w_root[i];
    }
    __syncthreads();

    int t = blockIdx.x * 256 + threadIdx.x;
    int node = t >> 2;
    if (node >= N_NODES) return;
    int part = t & 3;
    const float* w = (part < 2) ? sw : su;
    int jbase = (part & 1) * 8;

    float acc[8];
#pragma unroll
    for (int j = 0; j < 8; j++) acc[j] = 0.f;

    const float4* xr = reinterpret_cast<const float4*>(x + (size_t)node * IN_CH);
#pragma unroll
    for (int k4 = 0; k4 < IN_CH / 4; k4++) {
        float4 xv = __ldg(xr + k4);
        float xs[4] = {xv.x, xv.y, xv.z, xv.w};
#pragma unroll
        for (int u = 0; u < 4; u++) {
            int k = k4 * 4 + u;
            const float* wr = w + k * HID + jbase;
#pragma unroll
            for (int j = 0; j < 8; j++)
                acc[j] = fmaf(xs[u], wr[j], acc[j]);
        }
    }
    float* dst = ((part < 2) ? g_y1 : g_r1) + (size_t)node * HID + jbase;
    reinterpret_cast<float4*>(dst)[0] = make_float4(acc[0], acc[1], acc[2], acc[3]);
    reinterpret_cast<float4*>(dst)[1] = make_float4(acc[4], acc[5], acc[6], acc[7]);
}

// Gather aggregation layer 1: warp per node, 2 neighbors/iteration, 16 feats
__global__ __launch_bounds__(256) void k_gath1() {
    int warp = (blockIdx.x * 256 + threadIdx.x) >> 5;
    if (warp >= N_NODES) return;
    int lane = threadIdx.x & 31;
    int ro = g_row[warp], re = g_row[warp + 1];
    int f = lane & 15;
    int half = lane >> 4;

    float acc = 0.f;
    for (int i = ro + half; i < re; i += 2) {
        int s = __ldg(&g_adj[i]);
        acc += __ldg(&g_y1[(size_t)s * HID + f]);
    }
    acc += __shfl_down_sync(0xffffffff, acc, 16);
    if (lane < 16) g_agg1[(size_t)warp * HID + lane] = acc;
}

// h = relu(agg1 + b1 + r1); y2 = h @ w_rel2 (pad 12); r2 = h @ w_root2
__global__ __launch_bounds__(128) void k_lin2(const float* __restrict__ b1,
                                              const float* __restrict__ w_rel2,
                                              const float* __restrict__ w_root2) {
    __shared__ float sw[HID * NCLS];
    __shared__ float su[HID * NCLS];
    __shared__ float sb[HID];
    for (int i = threadIdx.x; i < HID * NCLS; i += 128) {
        sw[i] = w_rel2[i];
        su[i] = w_root2[i];
    }
    if (threadIdx.x < HID) sb[threadIdx.x] = b1[threadIdx.x];
    __syncthreads();

    int node = blockIdx.x * 128 + threadIdx.x;
    if (node >= N_NODES) return;

    float h[HID];
#pragma unroll
    for (int j = 0; j < HID; j++) {
        float v = g_agg1[(size_t)node * HID + j] + sb[j] + g_r1[(size_t)node * HID + j];
        h[j] = v > 0.f ? v : 0.f;
    }
    float y[NCLS], r[NCLS];
#pragma unroll
    for (int c = 0; c < NCLS; c++) { y[c] = 0.f; r[c] = 0.f; }
#pragma unroll
    for (int j = 0; j < HID; j++) {
#pragma unroll
        for (int c = 0; c < NCLS; c++) {
            y[c] = fmaf(h[j], sw[j * NCLS + c], y[c]);
            r[c] = fmaf(h[j], su[j * NCLS + c], r[c]);
        }
    }
    float* y2 = g_y2 + (size_t)node * HID2P;
    float* r2 = g_r2 + (size_t)node * HID2P;
#pragma unroll
    for (int c = 0; c < NCLS; c++) { y2[c] = y[c]; r2[c] = r[c]; }
    y2[10] = 0.f; y2[11] = 0.f;
    r2[10] = 0.f; r2[11] = 0.f;
}

// Gather aggregation layer 2: warp per node, 12-wide rows
__global__ __launch_bounds__(256) void k_gath2() {
    int warp = (blockIdx.x * 256 + threadIdx.x) >> 5;
    if (warp >= N_NODES) return;
    int lane = threadIdx.x & 31;
    int ro = g_row[warp], re = g_row[warp + 1];
    int f = lane & 15;
    int half = lane >> 4;
    bool active = (f < HID2P);

    float acc = 0.f;
    for (int i = ro + half; i < re; i += 2) {
        int s = __ldg(&g_adj[i]);
        if (active) acc += __ldg(&g_y2[(size_t)s * HID2P + f]);
    }
    acc += __shfl_down_sync(0xffffffff, acc, 16);
    if (lane < HID2P) g_agg2[(size_t)warp * HID2P + lane] = acc;
}

// out = log_softmax(agg2 + b2 + r2)
__global__ __launch_bounds__(128) void k_out(const float* __restrict__ b2,
                                             float* __restrict__ out) {
    __shared__ float sb[NCLS];
    if (threadIdx.x < NCLS) sb[threadIdx.x] = b2[threadIdx.x];
    __syncthreads();

    int node = blockIdx.x * 128 + threadIdx.x;
    if (node >= N_NODES) return;

    float o[NCLS];
#pragma unroll
    for (int c = 0; c < NCLS; c++)
        o[c] = g_agg2[(size_t)node * HID2P + c] + sb[c] + g_r2[(size_t)node * HID2P + c];

    float m = o[0];
#pragma unroll
    for (int c = 1; c < NCLS; c++) m = fmaxf(m, o[c]);
    float sum = 0.f;
#pragma unroll
    for (int c = 0; c < NCLS; c++) sum += __expf(o[c] - m);
    float ls = m + logf(sum);
#pragma unroll
    for (int c = 0; c < NCLS; c++)
        out[(size_t)node * NCLS + c] = o[c] - ls;
}

// ---------------- launch ----------------
extern "C" void kernel_launch(void* const* d_in, const int* in_sizes, int n_in,
                              void* d_out, int out_size) {
    const float* x       = (const float*)d_in[0];
    const void*  ei      = d_in[1];
    const float* w_rel1  = (const float*)d_in[2];
    const float* b_rel1  = (const float*)d_in[3];
    const float* w_root1 = (const float*)d_in[4];
    const float* w_rel2  = (const float*)d_in[5];
    const float* b_rel2  = (const float*)d_in[6];
    const float* w_root2 = (const float*)d_in[7];
    float* out = (float*)d_out;

    const int edgeBlocks  = (N_EDGES + 255) / 256;
    const int lin1Blocks  = (N_NODES * 4 + 255) / 256;
    const int nodeBlocks  = (N_NODES + 127) / 128;
    const int gathBlocks  = (N_NODES * 32 + 255) / 256;

    k_detect<<<1, 256>>>((const int*)ei);
    k_zero<<<256, 256>>>();
    k_lin1<<<lin1Blocks, 256>>>(x, w_rel1, w_root1);
    k_hist<<<edgeBlocks, 256>>>(ei);
    k_scan<<<1, 1024>>>();
    k_fill<<<edgeBlocks, 256>>>(ei);
    k_gath1<<<gathBlocks, 256>>>();
    k_lin2<<<nodeBlocks, 128>>>(b_rel1, w_rel2, w_root2);
    k_gath2<<<gathBlocks, 256>>>();
    k_out<<<nodeBlocks, 128>>>(b_rel2, out);
}

// round 4
// speedup vs baseline: 1.9825x; 1.9825x over previous
#include <cuda_runtime.h>
#include <cuda_bf16.h>
#include <math.h>

#define N_NODES  50000
#define N_EDGES  1600000
#define IN_CH    64
#define HID      16
#define NCLS     10
#define HID2P    12

// ---------------- device scratch ----------------
__device__ __align__(16) float g_y1  [N_NODES * HID];    // x @ w_rel1
__device__ __align__(16) float g_r1  [N_NODES * HID];    // x @ w_root1
__device__ __align__(16) float g_agg1[N_NODES * HID];    // segment_sum(y1)
__device__ __align__(16) float g_y2  [N_NODES * HID2P];  // h @ w_rel2 (padded)
__device__ __align__(16) float g_r2  [N_NODES * HID2P];  // h @ w_root2
__device__ __align__(16) float g_agg2[N_NODES * HID2P];  // segment_sum(y2)
__device__ int g_is64;                                   // edge dtype flag

// ---------------- kernels ----------------

// Detect edge index dtype: int64 values < 2^31 -> all odd 32-bit words zero.
__global__ void k_detect(const int* __restrict__ ei32) {
    __shared__ int s_or;
    if (threadIdx.x == 0) s_or = 0;
    __syncthreads();
    int v = 0;
    for (int i = threadIdx.x; i < 1024; i += blockDim.x)
        v |= ei32[2 * i + 1];
    if (v) atomicOr(&s_or, 1);
    __syncthreads();
    if (threadIdx.x == 0) g_is64 = (s_or == 0) ? 1 : 0;
}

// Zero both aggregation buffers (float4 grid-stride)
__global__ void k_zero() {
    const int n1 = N_NODES * HID / 4;     // 200000 float4
    const int n2 = N_NODES * HID2P / 4;   // 150000 float4
    float4 z = make_float4(0.f, 0.f, 0.f, 0.f);
    for (int i = blockIdx.x * blockDim.x + threadIdx.x; i < n1 + n2;
         i += gridDim.x * blockDim.x) {
        if (i < n1) reinterpret_cast<float4*>(g_agg1)[i] = z;
        else        reinterpret_cast<float4*>(g_agg2)[i - n1] = z;
    }
}

// Layer-1 projections, 4-way split: thread = node*4 + part
// part: 0 -> rel cols 0-7, 1 -> rel 8-15, 2 -> root 0-7, 3 -> root 8-15
__global__ __launch_bounds__(256) void k_lin1(const float* __restrict__ x,
                                              const float* __restrict__ w_rel,
                                              const float* __restrict__ w_root) {
    __shared__ float sw[IN_CH * HID];
    __shared__ float su[IN_CH * HID];
    for (int i = threadIdx.x; i < IN_CH * HID; i += 256) {
        sw[i] = w_rel[i];
        su[i] = w_root[i];
    }
    __syncthreads();

    int t = blockIdx.x * 256 + threadIdx.x;
    int node = t >> 2;
    if (node >= N_NODES) return;
    int part = t & 3;
    const float* w = (part < 2) ? sw : su;
    int jbase = (part & 1) * 8;

    float acc[8];
#pragma unroll
    for (int j = 0; j < 8; j++) acc[j] = 0.f;

    const float4* xr = reinterpret_cast<const float4*>(x + (size_t)node * IN_CH);
#pragma unroll
    for (int k4 = 0; k4 < IN_CH / 4; k4++) {
        float4 xv = __ldg(xr + k4);
        float xs[4] = {xv.x, xv.y, xv.z, xv.w};
#pragma unroll
        for (int u = 0; u < 4; u++) {
            int k = k4 * 4 + u;
            const float* wr = w + k * HID + jbase;
#pragma unroll
            for (int j = 0; j < 8; j++)
                acc[j] = fmaf(xs[u], wr[j], acc[j]);
        }
    }
    float* dst = ((part < 2) ? g_y1 : g_r1) + (size_t)node * HID + jbase;
    reinterpret_cast<float4*>(dst)[0] = make_float4(acc[0], acc[1], acc[2], acc[3]);
    reinterpret_cast<float4*>(dst)[1] = make_float4(acc[4], acc[5], acc[6], acc[7]);
}

// Layer-1 scatter: thread = edge*4 + quarter. Each thread moves one float4.
// 4 lanes of a warp handle one edge -> 64B row gather is lane-coalesced.
__global__ __launch_bounds__(256) void k_scat1(const void* __restrict__ ei) {
    const bool is64 = (g_is64 != 0);
    int t = blockIdx.x * 256 + threadIdx.x;
    int e = t >> 2;
    if (e >= N_EDGES) return;
    int q = t & 3;
    int s, d;
    if (is64) {
        const long long* p = (const long long*)ei;
        s = (int)p[e];
        d = (int)p[N_EDGES + e];
    } else {
        const int* p = (const int*)ei;
        s = p[e];
        d = p[N_EDGES + e];
    }
    float4 v = __ldg(reinterpret_cast<const float4*>(g_y1 + (size_t)s * HID) + q);
    float* dstp = g_agg1 + (size_t)d * HID + q * 4;
    asm volatile("red.global.add.v4.f32 [%0], {%1, %2, %3, %4};"
                 :: "l"(dstp), "f"(v.x), "f"(v.y), "f"(v.z), "f"(v.w)
                 : "memory");
}

// h = relu(agg1 + b1 + r1); y2 = h @ w_rel2 (pad 12); r2 = h @ w_root2
__global__ __launch_bounds__(128) void k_lin2(const float* __restrict__ b1,
                                              const float* __restrict__ w_rel2,
                                              const float* __restrict__ w_root2) {
    __shared__ float sw[HID * NCLS];
    __shared__ float su[HID * NCLS];
    __shared__ float sb[HID];
    for (int i = threadIdx.x; i < HID * NCLS; i += 128) {
        sw[i] = w_rel2[i];
        su[i] = w_root2[i];
    }
    if (threadIdx.x < HID) sb[threadIdx.x] = b1[threadIdx.x];
    __syncthreads();

    int node = blockIdx.x * 128 + threadIdx.x;
    if (node >= N_NODES) return;

    float h[HID];
#pragma unroll
    for (int j = 0; j < HID; j++) {
        float v = g_agg1[(size_t)node * HID + j] + sb[j] + g_r1[(size_t)node * HID + j];
        h[j] = v > 0.f ? v : 0.f;
    }
    float y[NCLS], r[NCLS];
#pragma unroll
    for (int c = 0; c < NCLS; c++) { y[c] = 0.f; r[c] = 0.f; }
#pragma unroll
    for (int j = 0; j < HID; j++) {
#pragma unroll
        for (int c = 0; c < NCLS; c++) {
            y[c] = fmaf(h[j], sw[j * NCLS + c], y[c]);
            r[c] = fmaf(h[j], su[j * NCLS + c], r[c]);
        }
    }
    float* y2 = g_y2 + (size_t)node * HID2P;
    float* r2 = g_r2 + (size_t)node * HID2P;
#pragma unroll
    for (int c = 0; c < NCLS; c++) { y2[c] = y[c]; r2[c] = r[c]; }
    y2[10] = 0.f; y2[11] = 0.f;
    r2[10] = 0.f; r2[11] = 0.f;
}

// Layer-2 scatter: thread = edge*3 + third (exact mapping, no idle lanes).
__global__ __launch_bounds__(256) void k_scat2(const void* __restrict__ ei) {
    const bool is64 = (g_is64 != 0);
    unsigned t = blockIdx.x * 256 + threadIdx.x;
    if (t >= 3u * N_EDGES) return;
    unsigned e = (unsigned)(((unsigned long long)t * 0x55555556ULL) >> 32);  // t/3
    unsigned q = t - e * 3u;
    int s, d;
    if (is64) {
        const long long* p = (const long long*)ei;
        s = (int)p[e];
        d = (int)p[N_EDGES + e];
    } else {
        const int* p = (const int*)ei;
        s = p[e];
        d = p[N_EDGES + e];
    }
    float4 v = __ldg(reinterpret_cast<const float4*>(g_y2 + (size_t)s * HID2P) + q);
    float* dstp = g_agg2 + (size_t)d * HID2P + q * 4;
    asm volatile("red.global.add.v4.f32 [%0], {%1, %2, %3, %4};"
                 :: "l"(dstp), "f"(v.x), "f"(v.y), "f"(v.z), "f"(v.w)
                 : "memory");
}

// out = log_softmax(agg2 + b2 + r2)
__global__ __launch_bounds__(128) void k_out(const float* __restrict__ b2,
                                             float* __restrict__ out) {
    __shared__ float sb[NCLS];
    if (threadIdx.x < NCLS) sb[threadIdx.x] = b2[threadIdx.x];
    __syncthreads();

    int node = blockIdx.x * 128 + threadIdx.x;
    if (node >= N_NODES) return;

    float o[NCLS];
#pragma unroll
    for (int c = 0; c < NCLS; c++)
        o[c] = g_agg2[(size_t)node * HID2P + c] + sb[c] + g_r2[(size_t)node * HID2P + c];

    float m = o[0];
#pragma unroll
    for (int c = 1; c < NCLS; c++) m = fmaxf(m, o[c]);
    float sum = 0.f;
#pragma unroll
    for (int c = 0; c < NCLS; c++) sum += __expf(o[c] - m);
    float ls = m + logf(sum);
#pragma unroll
    for (int c = 0; c < NCLS; c++)
        out[(size_t)node * NCLS + c] = o[c] - ls;
}

// ---------------- launch ----------------
extern "C" void kernel_launch(void* const* d_in, const int* in_sizes, int n_in,
                              void* d_out, int out_size) {
    const float* x       = (const float*)d_in[0];
    const void*  ei      = d_in[1];
    const float* w_rel1  = (const float*)d_in[2];
    const float* b_rel1  = (const float*)d_in[3];
    const float* w_root1 = (const float*)d_in[4];
    const float* w_rel2  = (const float*)d_in[5];
    const float* b_rel2  = (const float*)d_in[6];
    const float* w_root2 = (const float*)d_in[7];
    float* out = (float*)d_out;

    const int lin1Blocks  = (N_NODES * 4 + 255) / 256;
    const int nodeBlocks  = (N_NODES + 127) / 128;
    const int scat1Blocks = (N_EDGES * 4 + 255) / 256;
    const int scat2Blocks = (N_EDGES * 3 + 255) / 256;

    k_detect<<<1, 256>>>((const int*)ei);
    k_zero<<<512, 256>>>();
    k_lin1<<<lin1Blocks, 256>>>(x, w_rel1, w_root1);
    k_scat1<<<scat1Blocks, 256>>>(ei);
    k_lin2<<<nodeBlocks, 128>>>(b_rel1, w_rel2, w_root2);
    k_scat2<<<scat2Blocks, 256>>>(ei);
    k_out<<<nodeBlocks, 128>>>(b_rel2, out);
}

// round 5
// speedup vs baseline: 2.0600x; 1.0391x over previous
#include <cuda_runtime.h>
#include <cuda_bf16.h>
#include <math.h>

#define N_NODES  50000
#define N_EDGES  1600000
#define EHALF    (N_EDGES / 2)
#define IN_CH    64
#define HID      16
#define NCLS     10
#define HID2P    12

// ---------------- device scratch ----------------
__device__ __align__(16) float g_y1  [N_NODES * HID];    // x @ w_rel1
__device__ __align__(16) float g_r1  [N_NODES * HID];    // x @ w_root1
__device__ __align__(16) float g_agg1[N_NODES * HID];    // segment_sum(y1)
__device__ __align__(16) float g_y2  [N_NODES * HID2P];  // h @ w_rel2 (padded)
__device__ __align__(16) float g_r2  [N_NODES * HID2P];  // h @ w_root2
__device__ __align__(16) float g_agg2[N_NODES * HID2P];  // segment_sum(y2)
__device__ int g_is64;                                   // edge dtype flag

// ---------------- kernels ----------------

// Layer-1 projections + agg-buffer zeroing + dtype detection, fused.
// thread = node*4 + part; part: 0/1 -> rel cols 0-7 / 8-15, 2/3 -> root.
// Last block instead detects edge dtype (int64 -> odd 32-bit words all zero).
__global__ __launch_bounds__(256) void k_lin1(const float* __restrict__ x,
                                              const float* __restrict__ w_rel,
                                              const float* __restrict__ w_root,
                                              const int* __restrict__ ei32) {
    if (blockIdx.x == gridDim.x - 1) {
        __shared__ int s_or;
        if (threadIdx.x == 0) s_or = 0;
        __syncthreads();
        int v = 0;
        for (int i = threadIdx.x; i < 1024; i += 256)
            v |= ei32[2 * i + 1];
        if (v) atomicOr(&s_or, 1);
        __syncthreads();
        if (threadIdx.x == 0) g_is64 = (s_or == 0) ? 1 : 0;
        return;
    }

    __shared__ float sw[IN_CH * HID];
    __shared__ float su[IN_CH * HID];
    for (int i = threadIdx.x; i < IN_CH * HID; i += 256) {
        sw[i] = w_rel[i];
        su[i] = w_root[i];
    }
    __syncthreads();

    int t = blockIdx.x * 256 + threadIdx.x;
    int node = t >> 2;
    if (node >= N_NODES) return;
    int part = t & 3;

    // Zero this thread's slice of the aggregation buffers (fire-and-forget).
    float4 z = make_float4(0.f, 0.f, 0.f, 0.f);
    if (part < 2) {
        float4* az = reinterpret_cast<float4*>(g_agg1 + (size_t)node * HID + part * 8);
        az[0] = z; az[1] = z;
    } else if (part == 2) {
        float4* az = reinterpret_cast<float4*>(g_agg2 + (size_t)node * HID2P);
        az[0] = z; az[1] = z;
    } else {
        float4* az = reinterpret_cast<float4*>(g_agg2 + (size_t)node * HID2P + 8);
        az[0] = z;
    }

    const float* w = (part < 2) ? sw : su;
    int jbase = (part & 1) * 8;

    float acc[8];
#pragma unroll
    for (int j = 0; j < 8; j++) acc[j] = 0.f;

    const float4* xr = reinterpret_cast<const float4*>(x + (size_t)node * IN_CH);
#pragma unroll
    for (int k4 = 0; k4 < IN_CH / 4; k4++) {
        float4 xv = __ldg(xr + k4);
        float xs[4] = {xv.x, xv.y, xv.z, xv.w};
#pragma unroll
        for (int u = 0; u < 4; u++) {
            int k = k4 * 4 + u;
            const float* wr = w + k * HID + jbase;
#pragma unroll
            for (int j = 0; j < 8; j++)
                acc[j] = fmaf(xs[u], wr[j], acc[j]);
        }
    }
    float* dst = ((part < 2) ? g_y1 : g_r1) + (size_t)node * HID + jbase;
    reinterpret_cast<float4*>(dst)[0] = make_float4(acc[0], acc[1], acc[2], acc[3]);
    reinterpret_cast<float4*>(dst)[1] = make_float4(acc[4], acc[5], acc[6], acc[7]);
}

// Layer-1 scatter, ILP=2: thread = (e, quarter), handles edges e and e+EHALF.
__global__ __launch_bounds__(256) void k_scat1(const void* __restrict__ ei) {
    const bool is64 = (g_is64 != 0);
    int t = blockIdx.x * 256 + threadIdx.x;
    int e = t >> 2;
    if (e >= EHALF) return;
    int q = t & 3;
    int e2 = e + EHALF;
    int s0, d0, s1, d1;
    if (is64) {
        const long long* p = (const long long*)ei;
        s0 = (int)p[e];            s1 = (int)p[e2];
        d0 = (int)p[N_EDGES + e];  d1 = (int)p[N_EDGES + e2];
    } else {
        const int* p = (const int*)ei;
        s0 = p[e];            s1 = p[e2];
        d0 = p[N_EDGES + e];  d1 = p[N_EDGES + e2];
    }
    float4 v0 = __ldg(reinterpret_cast<const float4*>(g_y1 + (size_t)s0 * HID) + q);
    float4 v1 = __ldg(reinterpret_cast<const float4*>(g_y1 + (size_t)s1 * HID) + q);
    float* p0 = g_agg1 + (size_t)d0 * HID + q * 4;
    float* p1 = g_agg1 + (size_t)d1 * HID + q * 4;
    asm volatile("red.global.add.v4.f32 [%0], {%1, %2, %3, %4};"
                 :: "l"(p0), "f"(v0.x), "f"(v0.y), "f"(v0.z), "f"(v0.w) : "memory");
    asm volatile("red.global.add.v4.f32 [%0], {%1, %2, %3, %4};"
                 :: "l"(p1), "f"(v1.x), "f"(v1.y), "f"(v1.z), "f"(v1.w) : "memory");
}

// h = relu(agg1 + b1 + r1); y2 = h @ w_rel2 (pad 12); r2 = h @ w_root2
__global__ __launch_bounds__(128) void k_lin2(const float* __restrict__ b1,
                                              const float* __restrict__ w_rel2,
                                              const float* __restrict__ w_root2) {
    __shared__ float sw[HID * NCLS];
    __shared__ float su[HID * NCLS];
    __shared__ float sb[HID];
    for (int i = threadIdx.x; i < HID * NCLS; i += 128) {
        sw[i] = w_rel2[i];
        su[i] = w_root2[i];
    }
    if (threadIdx.x < HID) sb[threadIdx.x] = b1[threadIdx.x];
    __syncthreads();

    int node = blockIdx.x * 128 + threadIdx.x;
    if (node >= N_NODES) return;

    float h[HID];
#pragma unroll
    for (int j = 0; j < HID; j++) {
        float v = g_agg1[(size_t)node * HID + j] + sb[j] + g_r1[(size_t)node * HID + j];
        h[j] = v > 0.f ? v : 0.f;
    }
    float y[NCLS], r[NCLS];
#pragma unroll
    for (int c = 0; c < NCLS; c++) { y[c] = 0.f; r[c] = 0.f; }
#pragma unroll
    for (int j = 0; j < HID; j++) {
#pragma unroll
        for (int c = 0; c < NCLS; c++) {
            y[c] = fmaf(h[j], sw[j * NCLS + c], y[c]);
            r[c] = fmaf(h[j], su[j * NCLS + c], r[c]);
        }
    }
    float* y2 = g_y2 + (size_t)node * HID2P;
    float* r2 = g_r2 + (size_t)node * HID2P;
#pragma unroll
    for (int c = 0; c < NCLS; c++) { y2[c] = y[c]; r2[c] = r[c]; }
    y2[10] = 0.f; y2[11] = 0.f;
    r2[10] = 0.f; r2[11] = 0.f;
}

// Layer-2 scatter, ILP=2: thread = (e, third), edges e and e+EHALF.
__global__ __launch_bounds__(256) void k_scat2(const void* __restrict__ ei) {
    const bool is64 = (g_is64 != 0);
    unsigned t = blockIdx.x * 256 + threadIdx.x;
    if (t >= 3u * EHALF) return;
    unsigned e = (unsigned)(((unsigned long long)t * 0x55555556ULL) >> 32);  // t/3
    unsigned q = t - e * 3u;
    unsigned e2 = e + EHALF;
    int s0, d0, s1, d1;
    if (is64) {
        const long long* p = (const long long*)ei;
        s0 = (int)p[e];            s1 = (int)p[e2];
        d0 = (int)p[N_EDGES + e];  d1 = (int)p[N_EDGES + e2];
    } else {
        const int* p = (const int*)ei;
        s0 = p[e];            s1 = p[e2];
        d0 = p[N_EDGES + e];  d1 = p[N_EDGES + e2];
    }
    float4 v0 = __ldg(reinterpret_cast<const float4*>(g_y2 + (size_t)s0 * HID2P) + q);
    float4 v1 = __ldg(reinterpret_cast<const float4*>(g_y2 + (size_t)s1 * HID2P) + q);
    float* p0 = g_agg2 + (size_t)d0 * HID2P + q * 4;
    float* p1 = g_agg2 + (size_t)d1 * HID2P + q * 4;
    asm volatile("red.global.add.v4.f32 [%0], {%1, %2, %3, %4};"
                 :: "l"(p0), "f"(v0.x), "f"(v0.y), "f"(v0.z), "f"(v0.w) : "memory");
    asm volatile("red.global.add.v4.f32 [%0], {%1, %2, %3, %4};"
                 :: "l"(p1), "f"(v1.x), "f"(v1.y), "f"(v1.z), "f"(v1.w) : "memory");
}

// out = log_softmax(agg2 + b2 + r2)
__global__ __launch_bounds__(128) void k_out(const float* __restrict__ b2,
                                             float* __restrict__ out) {
    __shared__ float sb[NCLS];
    if (threadIdx.x < NCLS) sb[threadIdx.x] = b2[threadIdx.x];
    __syncthreads();

    int node = blockIdx.x * 128 + threadIdx.x;
    if (node >= N_NODES) return;

    float o[NCLS];
#pragma unroll
    for (int c = 0; c < NCLS; c++)
        o[c] = g_agg2[(size_t)node * HID2P + c] + sb[c] + g_r2[(size_t)node * HID2P + c];

    float m = o[0];
#pragma unroll
    for (int c = 1; c < NCLS; c++) m = fmaxf(m, o[c]);
    float sum = 0.f;
#pragma unroll
    for (int c = 0; c < NCLS; c++) sum += __expf(o[c] - m);
    float ls = m + logf(sum);
#pragma unroll
    for (int c = 0; c < NCLS; c++)
        out[(size_t)node * NCLS + c] = o[c] - ls;
}

// ---------------- launch ----------------
extern "C" void kernel_launch(void* const* d_in, const int* in_sizes, int n_in,
                              void* d_out, int out_size) {
    const float* x       = (const float*)d_in[0];
    const void*  ei      = d_in[1];
    const float* w_rel1  = (const float*)d_in[2];
    const float* b_rel1  = (const float*)d_in[3];
    const float* w_root1 = (const float*)d_in[4];
    const float* w_rel2  = (const float*)d_in[5];
    const float* b_rel2  = (const float*)d_in[6];
    const float* w_root2 = (const float*)d_in[7];
    float* out = (float*)d_out;

    const int lin1Blocks  = (N_NODES * 4 + 255) / 256 + 1;  // +1 detector block
    const int nodeBlocks  = (N_NODES + 127) / 128;
    const int scat1Blocks = (EHALF * 4 + 255) / 256;
    const int scat2Blocks = ((int)(3u * EHALF) + 255) / 256;

    k_lin1<<<lin1Blocks, 256>>>(x, w_rel1, w_root1, (const int*)ei);
    k_scat1<<<scat1Blocks, 256>>>(ei);
    k_lin2<<<nodeBlocks, 128>>>(b_rel1, w_rel2, w_root2);
    k_scat2<<<scat2Blocks, 256>>>(ei);
    k_out<<<nodeBlocks, 128>>>(b_rel2, out);
}

// round 6
// speedup vs baseline: 2.3676x; 1.1493x over previous
#include <cuda_runtime.h>
#include <cuda_bf16.h>
#include <math.h>

#define N_NODES  50000
#define N_EDGES  1600000
#define EQ       (N_EDGES / 4)
#define IN_CH    64
#define HID      16
#define NCLS     10
#define HID2P    12

// ---------------- device scratch ----------------
__device__ __align__(16) float g_y1  [N_NODES * HID];    // x @ w_rel1
__device__ __align__(16) float g_r1  [N_NODES * HID];    // x @ w_root1
__device__ __align__(16) float g_agg1[N_NODES * HID];    // segment_sum(y1)
__device__ __align__(16) float g_y2  [N_NODES * HID2P];  // h @ w_rel2 (padded)
__device__ __align__(16) float g_r2  [N_NODES * HID2P];  // h @ w_root2
__device__ __align__(16) float g_agg2[N_NODES * HID2P];  // segment_sum(y2)
__device__ int g_is64;                                   // edge dtype flag

// ---------------- kernels ----------------

// Layer-1 projections + agg zeroing + dtype detection.
// thread = pair*4 + part, pair covers nodes {2p, 2p+1}.
// part 0/1: rel cols 0-7 / 8-15 for both nodes; part 2/3: root.
// Each weight smem read is reused for 2 nodes (halves LDS traffic).
__global__ __launch_bounds__(256) void k_lin1(const float* __restrict__ x,
                                              const float* __restrict__ w_rel,
                                              const float* __restrict__ w_root,
                                              const int* __restrict__ ei32) {
    if (blockIdx.x == gridDim.x - 1) {
        __shared__ int s_or;
        if (threadIdx.x == 0) s_or = 0;
        __syncthreads();
        int v = 0;
        for (int i = threadIdx.x; i < 1024; i += 256)
            v |= ei32[2 * i + 1];
        if (v) atomicOr(&s_or, 1);
        __syncthreads();
        if (threadIdx.x == 0) g_is64 = (s_or == 0) ? 1 : 0;
        return;
    }

    __shared__ float sw[IN_CH * HID];
    __shared__ float su[IN_CH * HID];
    for (int i = threadIdx.x; i < IN_CH * HID; i += 256) {
        sw[i] = w_rel[i];
        su[i] = w_root[i];
    }
    __syncthreads();

    int t = blockIdx.x * 256 + threadIdx.x;
    int pair = t >> 2;
    if (pair >= N_NODES / 2) return;
    int part = t & 3;
    int n0 = pair * 2;
    int n1 = n0 + 1;

    // Zero agg slices (each part owns a disjoint region for this pair).
    float4 z = make_float4(0.f, 0.f, 0.f, 0.f);
    if (part == 0) {
        float4* az = reinterpret_cast<float4*>(g_agg1 + (size_t)n0 * HID);
        az[0] = z; az[1] = z; az[2] = z; az[3] = z;
    } else if (part == 1) {
        float4* az = reinterpret_cast<float4*>(g_agg1 + (size_t)n1 * HID);
        az[0] = z; az[1] = z; az[2] = z; az[3] = z;
    } else if (part == 2) {
        float4* az = reinterpret_cast<float4*>(g_agg2 + (size_t)n0 * HID2P);
        az[0] = z; az[1] = z; az[2] = z;
    } else {
        float4* az = reinterpret_cast<float4*>(g_agg2 + (size_t)n1 * HID2P);
        az[0] = z; az[1] = z; az[2] = z;
    }

    const float* w = (part < 2) ? sw : su;
    int jbase = (part & 1) * 8;

    float a0[8], a1[8];
#pragma unroll
    for (int j = 0; j < 8; j++) { a0[j] = 0.f; a1[j] = 0.f; }

    const float4* x0 = reinterpret_cast<const float4*>(x + (size_t)n0 * IN_CH);
    const float4* x1 = reinterpret_cast<const float4*>(x + (size_t)n1 * IN_CH);
#pragma unroll
    for (int k4 = 0; k4 < IN_CH / 4; k4++) {
        float4 v0 = __ldg(x0 + k4);
        float4 v1 = __ldg(x1 + k4);
        float s0[4] = {v0.x, v0.y, v0.z, v0.w};
        float s1[4] = {v1.x, v1.y, v1.z, v1.w};
#pragma unroll
        for (int u = 0; u < 4; u++) {
            int k = k4 * 4 + u;
            const float* wr = w + k * HID + jbase;
#pragma unroll
            for (int j = 0; j < 8; j++) {
                float wv = wr[j];                 // one smem read, two FMAs
                a0[j] = fmaf(s0[u], wv, a0[j]);
                a1[j] = fmaf(s1[u], wv, a1[j]);
            }
        }
    }
    float* base = (part < 2) ? g_y1 : g_r1;
    float* d0 = base + (size_t)n0 * HID + jbase;
    float* d1 = base + (size_t)n1 * HID + jbase;
    reinterpret_cast<float4*>(d0)[0] = make_float4(a0[0], a0[1], a0[2], a0[3]);
    reinterpret_cast<float4*>(d0)[1] = make_float4(a0[4], a0[5], a0[6], a0[7]);
    reinterpret_cast<float4*>(d1)[0] = make_float4(a1[0], a1[1], a1[2], a1[3]);
    reinterpret_cast<float4*>(d1)[1] = make_float4(a1[4], a1[5], a1[6], a1[7]);
}

// Layer-1 scatter, ILP=4: thread = (e, quarter), edges e + i*EQ, i<4.
__global__ __launch_bounds__(256) void k_scat1(const void* __restrict__ ei) {
    const bool is64 = (g_is64 != 0);
    int t = blockIdx.x * 256 + threadIdx.x;
    int e = t >> 2;
    if (e >= EQ) return;
    int q = t & 3;
    int s[4], d[4];
    if (is64) {
        const long long* p = (const long long*)ei;
#pragma unroll
        for (int i = 0; i < 4; i++) {
            s[i] = (int)p[e + i * EQ];
            d[i] = (int)p[N_EDGES + e + i * EQ];
        }
    } else {
        const int* p = (const int*)ei;
#pragma unroll
        for (int i = 0; i < 4; i++) {
            s[i] = p[e + i * EQ];
            d[i] = p[N_EDGES + e + i * EQ];
        }
    }
    float4 v[4];
#pragma unroll
    for (int i = 0; i < 4; i++)
        v[i] = __ldg(reinterpret_cast<const float4*>(g_y1 + (size_t)s[i] * HID) + q);
#pragma unroll
    for (int i = 0; i < 4; i++) {
        float* dp = g_agg1 + (size_t)d[i] * HID + q * 4;
        asm volatile("red.global.add.v4.f32 [%0], {%1, %2, %3, %4};"
                     :: "l"(dp), "f"(v[i].x), "f"(v[i].y), "f"(v[i].z), "f"(v[i].w)
                     : "memory");
    }
}

// h = relu(agg1 + b1 + r1); y2 = h @ w_rel2 (pad 12); r2 = h @ w_root2
__global__ __launch_bounds__(128) void k_lin2(const float* __restrict__ b1,
                                              const float* __restrict__ w_rel2,
                                              const float* __restrict__ w_root2) {
    __shared__ float sw[HID * NCLS];
    __shared__ float su[HID * NCLS];
    __shared__ float sb[HID];
    for (int i = threadIdx.x; i < HID * NCLS; i += 128) {
        sw[i] = w_rel2[i];
        su[i] = w_root2[i];
    }
    if (threadIdx.x < HID) sb[threadIdx.x] = b1[threadIdx.x];
    __syncthreads();

    int node = blockIdx.x * 128 + threadIdx.x;
    if (node >= N_NODES) return;

    float h[HID];
#pragma unroll
    for (int j = 0; j < HID; j++) {
        float v = g_agg1[(size_t)node * HID + j] + sb[j] + g_r1[(size_t)node * HID + j];
        h[j] = v > 0.f ? v : 0.f;
    }
    float y[NCLS], r[NCLS];
#pragma unroll
    for (int c = 0; c < NCLS; c++) { y[c] = 0.f; r[c] = 0.f; }
#pragma unroll
    for (int j = 0; j < HID; j++) {
#pragma unroll
        for (int c = 0; c < NCLS; c++) {
            y[c] = fmaf(h[j], sw[j * NCLS + c], y[c]);
            r[c] = fmaf(h[j], su[j * NCLS + c], r[c]);
        }
    }
    float* y2 = g_y2 + (size_t)node * HID2P;
    float* r2 = g_r2 + (size_t)node * HID2P;
#pragma unroll
    for (int c = 0; c < NCLS; c++) { y2[c] = y[c]; r2[c] = r[c]; }
    y2[10] = 0.f; y2[11] = 0.f;
    r2[10] = 0.f; r2[11] = 0.f;
}

// Layer-2 scatter, ILP=4: thread = (e, third), edges e + i*EQ, i<4.
__global__ __launch_bounds__(256) void k_scat2(const void* __restrict__ ei) {
    const bool is64 = (g_is64 != 0);
    unsigned t = blockIdx.x * 256 + threadIdx.x;
    if (t >= 3u * EQ) return;
    unsigned e = (unsigned)(((unsigned long long)t * 0x55555556ULL) >> 32);  // t/3
    unsigned q = t - e * 3u;
    int s[4], d[4];
    if (is64) {
        const long long* p = (const long long*)ei;
#pragma unroll
        for (int i = 0; i < 4; i++) {
            s[i] = (int)p[e + i * EQ];
            d[i] = (int)p[N_EDGES + e + i * EQ];
        }
    } else {
        const int* p = (const int*)ei;
#pragma unroll
        for (int i = 0; i < 4; i++) {
            s[i] = p[e + i * EQ];
            d[i] = p[N_EDGES + e + i * EQ];
        }
    }
    float4 v[4];
#pragma unroll
    for (int i = 0; i < 4; i++)
        v[i] = __ldg(reinterpret_cast<const float4*>(g_y2 + (size_t)s[i] * HID2P) + q);
#pragma unroll
    for (int i = 0; i < 4; i++) {
        float* dp = g_agg2 + (size_t)d[i] * HID2P + q * 4;
        asm volatile("red.global.add.v4.f32 [%0], {%1, %2, %3, %4};"
                     :: "l"(dp), "f"(v[i].x), "f"(v[i].y), "f"(v[i].z), "f"(v[i].w)
                     : "memory");
    }
}

// out = log_softmax(agg2 + b2 + r2)
__global__ __launch_bounds__(128) void k_out(const float* __restrict__ b2,
                                             float* __restrict__ out) {
    __shared__ float sb[NCLS];
    if (threadIdx.x < NCLS) sb[threadIdx.x] = b2[threadIdx.x];
    __syncthreads();

    int node = blockIdx.x * 128 + threadIdx.x;
    if (node >= N_NODES) return;

    float o[NCLS];
#pragma unroll
    for (int c = 0; c < NCLS; c++)
        o[c] = g_agg2[(size_t)node * HID2P + c] + sb[c] + g_r2[(size_t)node * HID2P + c];

    float m = o[0];
#pragma unroll
    for (int c = 1; c < NCLS; c++) m = fmaxf(m, o[c]);
    float sum = 0.f;
#pragma unroll
    for (int c = 0; c < NCLS; c++) sum += __expf(o[c] - m);
    float ls = m + logf(sum);
#pragma unroll
    for (int c = 0; c < NCLS; c++)
        out[(size_t)node * NCLS + c] = o[c] - ls;
}

// ---------------- launch ----------------
extern "C" void kernel_launch(void* const* d_in, const int* in_sizes, int n_in,
                              void* d_out, int out_size) {
    const float* x       = (const float*)d_in[0];
    const void*  ei      = d_in[1];
    const float* w_rel1  = (const float*)d_in[2];
    const float* b_rel1  = (const float*)d_in[3];
    const float* w_root1 = (const float*)d_in[4];
    const float* w_rel2  = (const float*)d_in[5];
    const float* b_rel2  = (const float*)d_in[6];
    const float* w_root2 = (const float*)d_in[7];
    float* out = (float*)d_out;

    const int lin1Blocks  = (N_NODES / 2 * 4 + 255) / 256 + 1;  // +1 detector
    const int nodeBlocks  = (N_NODES + 127) / 128;
    const int scat1Blocks = (EQ * 4 + 255) / 256;
    const int scat2Blocks = ((int)(3u * EQ) + 255) / 256;

    k_lin1<<<lin1Blocks, 256>>>(x, w_rel1, w_root1, (const int*)ei);
    k_scat1<<<scat1Blocks, 256>>>(ei);
    k_lin2<<<nodeBlocks, 128>>>(b_rel1, w_rel2, w_root2);
    k_scat2<<<scat2Blocks, 256>>>(ei);
    k_out<<<nodeBlocks, 128>>>(b_rel2, out);
}

// round 7
// speedup vs baseline: 2.4860x; 1.0500x over previous
#include <cuda_runtime.h>
#include <cuda_bf16.h>
#include <math.h>

#define N_NODES  50000
#define N_EDGES  1600000
#define EQ       (N_EDGES / 4)
#define IN_CH    64
#define HID      16
#define NCLS     10
#define HID2P    12

// ---------------- device scratch ----------------
__device__ __align__(16) float g_y1  [N_NODES * HID];    // x @ w_rel1
__device__ __align__(16) float g_r1  [N_NODES * HID];    // x @ w_root1
__device__ __align__(16) float g_agg1[N_NODES * HID];    // segment_sum(y1)
__device__ __align__(16) float g_h   [N_NODES * HID];    // relu hidden
__device__ __align__(16) float g_y2  [N_NODES * HID2P];  // h @ w_rel2 (padded)
__device__ __align__(16) float g_r2  [N_NODES * HID2P];  // h @ w_root2
__device__ __align__(16) float g_agg2[N_NODES * HID2P];  // segment_sum(y2)
__device__ int g_is64;                                   // edge dtype flag

// ---------------- kernels ----------------

// y1 = x @ w_rel1, zero agg1, detect edge dtype (last block).
// thread = pair*4 + part; pair = nodes {2p,2p+1}; part = column quarter (4 cols).
// Weight smem reads reused across the 2 nodes.
__global__ __launch_bounds__(256) void k_lin1y(const float* __restrict__ x,
                                               const float* __restrict__ w_rel,
                                               const int* __restrict__ ei32) {
    if (blockIdx.x == gridDim.x - 1) {
        __shared__ int s_or;
        if (threadIdx.x == 0) s_or = 0;
        __syncthreads();
        int v = 0;
        for (int i = threadIdx.x; i < 1024; i += 256)
            v |= ei32[2 * i + 1];
        if (v) atomicOr(&s_or, 1);
        __syncthreads();
        if (threadIdx.x == 0) g_is64 = (s_or == 0) ? 1 : 0;
        return;
    }

    __shared__ float sw[IN_CH * HID];
    for (int i = threadIdx.x; i < IN_CH * HID; i += 256) sw[i] = w_rel[i];
    __syncthreads();

    int t = blockIdx.x * 256 + threadIdx.x;
    int pair = t >> 2;
    if (pair >= N_NODES / 2) return;
    int part = t & 3;
    int jbase = part * 4;
    int n0 = pair * 2, n1 = n0 + 1;

    // Zero agg1 for this pair: 8 float4s, 2 per part.
    {
        float4 z = make_float4(0.f, 0.f, 0.f, 0.f);
        float4* az = reinterpret_cast<float4*>(g_agg1 + (size_t)pair * 2 * HID);
        az[2 * part] = z;
        az[2 * part + 1] = z;
    }

    float a0[4] = {0.f, 0.f, 0.f, 0.f};
    float a1[4] = {0.f, 0.f, 0.f, 0.f};
    const float4* x0 = reinterpret_cast<const float4*>(x + (size_t)n0 * IN_CH);
    const float4* x1 = reinterpret_cast<const float4*>(x + (size_t)n1 * IN_CH);
#pragma unroll
    for (int k4 = 0; k4 < IN_CH / 4; k4++) {
        float4 v0 = __ldg(x0 + k4);
        float4 v1 = __ldg(x1 + k4);
        float s0[4] = {v0.x, v0.y, v0.z, v0.w};
        float s1[4] = {v1.x, v1.y, v1.z, v1.w};
#pragma unroll
        for (int u = 0; u < 4; u++) {
            const float* wr = sw + (k4 * 4 + u) * HID + jbase;
#pragma unroll
            for (int j = 0; j < 4; j++) {
                float wv = wr[j];
                a0[j] = fmaf(s0[u], wv, a0[j]);
                a1[j] = fmaf(s1[u], wv, a1[j]);
            }
        }
    }
    *reinterpret_cast<float4*>(g_y1 + (size_t)n0 * HID + jbase) =
        make_float4(a0[0], a0[1], a0[2], a0[3]);
    *reinterpret_cast<float4*>(g_y1 + (size_t)n1 * HID + jbase) =
        make_float4(a1[0], a1[1], a1[2], a1[3]);
}

// r1 = x @ w_root1, zero agg2. Same structure (runs on side stream).
__global__ __launch_bounds__(256) void k_lin1r(const float* __restrict__ x,
                                               const float* __restrict__ w_root) {
    __shared__ float su[IN_CH * HID];
    for (int i = threadIdx.x; i < IN_CH * HID; i += 256) su[i] = w_root[i];
    __syncthreads();

    int t = blockIdx.x * 256 + threadIdx.x;
    int pair = t >> 2;
    if (pair >= N_NODES / 2) return;
    int part = t & 3;
    int jbase = part * 4;
    int n0 = pair * 2, n1 = n0 + 1;

    // Zero agg2 for this pair: 6 float4s over 4 parts.
    {
        float4 z = make_float4(0.f, 0.f, 0.f, 0.f);
        float4* az = reinterpret_cast<float4*>(g_agg2 + (size_t)pair * 2 * HID2P);
        if (part == 0)      { az[0] = z; az[1] = z; }
        else if (part == 1) { az[2] = z; az[3] = z; }
        else if (part == 2) { az[4] = z; }
        else                { az[5] = z; }
    }

    float a0[4] = {0.f, 0.f, 0.f, 0.f};
    float a1[4] = {0.f, 0.f, 0.f, 0.f};
    const float4* x0 = reinterpret_cast<const float4*>(x + (size_t)n0 * IN_CH);
    const float4* x1 = reinterpret_cast<const float4*>(x + (size_t)n1 * IN_CH);
#pragma unroll
    for (int k4 = 0; k4 < IN_CH / 4; k4++) {
        float4 v0 = __ldg(x0 + k4);
        float4 v1 = __ldg(x1 + k4);
        float s0[4] = {v0.x, v0.y, v0.z, v0.w};
        float s1[4] = {v1.x, v1.y, v1.z, v1.w};
#pragma unroll
        for (int u = 0; u < 4; u++) {
            const float* wr = su + (k4 * 4 + u) * HID + jbase;
#pragma unroll
            for (int j = 0; j < 4; j++) {
                float wv = wr[j];
                a0[j] = fmaf(s0[u], wv, a0[j]);
                a1[j] = fmaf(s1[u], wv, a1[j]);
            }
        }
    }
    *reinterpret_cast<float4*>(g_r1 + (size_t)n0 * HID + jbase) =
        make_float4(a0[0], a0[1], a0[2], a0[3]);
    *reinterpret_cast<float4*>(g_r1 + (size_t)n1 * HID + jbase) =
        make_float4(a1[0], a1[1], a1[2], a1[3]);
}

// Layer-1 scatter, ILP=4: thread = (e, quarter), edges e + i*EQ.
__global__ __launch_bounds__(256) void k_scat1(const void* __restrict__ ei) {
    const bool is64 = (g_is64 != 0);
    int t = blockIdx.x * 256 + threadIdx.x;
    int e = t >> 2;
    if (e >= EQ) return;
    int q = t & 3;
    int s[4], d[4];
    if (is64) {
        const long long* p = (const long long*)ei;
#pragma unroll
        for (int i = 0; i < 4; i++) {
            s[i] = (int)p[e + i * EQ];
            d[i] = (int)p[N_EDGES + e + i * EQ];
        }
    } else {
        const int* p = (const int*)ei;
#pragma unroll
        for (int i = 0; i < 4; i++) {
            s[i] = p[e + i * EQ];
            d[i] = p[N_EDGES + e + i * EQ];
        }
    }
    float4 v[4];
#pragma unroll
    for (int i = 0; i < 4; i++)
        v[i] = __ldg(reinterpret_cast<const float4*>(g_y1 + (size_t)s[i] * HID) + q);
#pragma unroll
    for (int i = 0; i < 4; i++) {
        float* dp = g_agg1 + (size_t)d[i] * HID + q * 4;
        asm volatile("red.global.add.v4.f32 [%0], {%1, %2, %3, %4};"
                     :: "l"(dp), "f"(v[i].x), "f"(v[i].y), "f"(v[i].z), "f"(v[i].w)
                     : "memory");
    }
}

// h = relu(agg1 + b1 + r1) -> g_h ; y2 = h @ w_rel2 (padded to 12)
__global__ __launch_bounds__(128) void k_lin2h(const float* __restrict__ b1,
                                               const float* __restrict__ w_rel2) {
    __shared__ float sw[HID * NCLS];
    __shared__ float sb[HID];
    for (int i = threadIdx.x; i < HID * NCLS; i += 128) sw[i] = w_rel2[i];
    if (threadIdx.x < HID) sb[threadIdx.x] = b1[threadIdx.x];
    __syncthreads();

    int node = blockIdx.x * 128 + threadIdx.x;
    if (node >= N_NODES) return;

    float h[HID];
#pragma unroll
    for (int j = 0; j < HID; j++) {
        float v = g_agg1[(size_t)node * HID + j] + sb[j] + g_r1[(size_t)node * HID + j];
        h[j] = v > 0.f ? v : 0.f;
    }
    float4* hd = reinterpret_cast<float4*>(g_h + (size_t)node * HID);
#pragma unroll
    for (int q = 0; q < 4; q++)
        hd[q] = make_float4(h[q*4+0], h[q*4+1], h[q*4+2], h[q*4+3]);

    float y[NCLS];
#pragma unroll
    for (int c = 0; c < NCLS; c++) y[c] = 0.f;
#pragma unroll
    for (int j = 0; j < HID; j++)
#pragma unroll
        for (int c = 0; c < NCLS; c++)
            y[c] = fmaf(h[j], sw[j * NCLS + c], y[c]);

    float* y2 = g_y2 + (size_t)node * HID2P;
#pragma unroll
    for (int c = 0; c < NCLS; c++) y2[c] = y[c];
    y2[10] = 0.f; y2[11] = 0.f;
}

// r2 = h @ w_root2 (side stream, overlaps scat2)
__global__ __launch_bounds__(128) void k_lin2r(const float* __restrict__ w_root2) {
    __shared__ float su[HID * NCLS];
    for (int i = threadIdx.x; i < HID * NCLS; i += 128) su[i] = w_root2[i];
    __syncthreads();

    int node = blockIdx.x * 128 + threadIdx.x;
    if (node >= N_NODES) return;

    float h[HID];
    const float4* hs = reinterpret_cast<const float4*>(g_h + (size_t)node * HID);
#pragma unroll
    for (int q = 0; q < 4; q++) {
        float4 v = hs[q];
        h[q*4+0] = v.x; h[q*4+1] = v.y; h[q*4+2] = v.z; h[q*4+3] = v.w;
    }
    float r[NCLS];
#pragma unroll
    for (int c = 0; c < NCLS; c++) r[c] = 0.f;
#pragma unroll
    for (int j = 0; j < HID; j++)
#pragma unroll
        for (int c = 0; c < NCLS; c++)
            r[c] = fmaf(h[j], su[j * NCLS + c], r[c]);

    float* r2 = g_r2 + (size_t)node * HID2P;
#pragma unroll
    for (int c = 0; c < NCLS; c++) r2[c] = r[c];
}

// Layer-2 scatter, ILP=4: thread = (e, third), edges e + i*EQ.
__global__ __launch_bounds__(256) void k_scat2(const void* __restrict__ ei) {
    const bool is64 = (g_is64 != 0);
    unsigned t = blockIdx.x * 256 + threadIdx.x;
    if (t >= 3u * EQ) return;
    unsigned e = (unsigned)(((unsigned long long)t * 0x55555556ULL) >> 32);  // t/3
    unsigned q = t - e * 3u;
    int s[4], d[4];
    if (is64) {
        const long long* p = (const long long*)ei;
#pragma unroll
        for (int i = 0; i < 4; i++) {
            s[i] = (int)p[e + i * EQ];
            d[i] = (int)p[N_EDGES + e + i * EQ];
        }
    } else {
        const int* p = (const int*)ei;
#pragma unroll
        for (int i = 0; i < 4; i++) {
            s[i] = p[e + i * EQ];
            d[i] = p[N_EDGES + e + i * EQ];
        }
    }
    float4 v[4];
#pragma unroll
    for (int i = 0; i < 4; i++)
        v[i] = __ldg(reinterpret_cast<const float4*>(g_y2 + (size_t)s[i] * HID2P) + q);
#pragma unroll
    for (int i = 0; i < 4; i++) {
        float* dp = g_agg2 + (size_t)d[i] * HID2P + q * 4;
        asm volatile("red.global.add.v4.f32 [%0], {%1, %2, %3, %4};"
                     :: "l"(dp), "f"(v[i].x), "f"(v[i].y), "f"(v[i].z), "f"(v[i].w)
                     : "memory");
    }
}

// out = log_softmax(agg2 + b2 + r2)
__global__ __launch_bounds__(128) void k_out(const float* __restrict__ b2,
                                             float* __restrict__ out) {
    __shared__ float sb[NCLS];
    if (threadIdx.x < NCLS) sb[threadIdx.x] = b2[threadIdx.x];
    __syncthreads();

    int node = blockIdx.x * 128 + threadIdx.x;
    if (node >= N_NODES) return;

    float o[NCLS];
#pragma unroll
    for (int c = 0; c < NCLS; c++)
        o[c] = g_agg2[(size_t)node * HID2P + c] + sb[c] + g_r2[(size_t)node * HID2P + c];

    float m = o[0];
#pragma unroll
    for (int c = 1; c < NCLS; c++) m = fmaxf(m, o[c]);
    float sum = 0.f;
#pragma unroll
    for (int c = 0; c < NCLS; c++) sum += __expf(o[c] - m);
    float ls = m + logf(sum);
#pragma unroll
    for (int c = 0; c < NCLS; c++)
        out[(size_t)node * NCLS + c] = o[c] - ls;
}

// ---------------- launch ----------------
extern "C" void kernel_launch(void* const* d_in, const int* in_sizes, int n_in,
                              void* d_out, int out_size) {
    const float* x       = (const float*)d_in[0];
    const void*  ei      = d_in[1];
    const float* w_rel1  = (const float*)d_in[2];
    const float* b_rel1  = (const float*)d_in[3];
    const float* w_root1 = (const float*)d_in[4];
    const float* w_rel2  = (const float*)d_in[5];
    const float* b_rel2  = (const float*)d_in[6];
    const float* w_root2 = (const float*)d_in[7];
    float* out = (float*)d_out;

    // One-time stream/event setup. First call is the uncaptured correctness
    // run, so these exist before graph capture. Work enqueued is identical
    // on every call.
    static cudaStream_t s2 = nullptr;
    static cudaEvent_t ev0, evR1, evH, evR2;
    if (!s2) {
        cudaStreamCreateWithFlags(&s2, cudaStreamNonBlocking);
        cudaEventCreateWithFlags(&ev0,  cudaEventDisableTiming);
        cudaEventCreateWithFlags(&evR1, cudaEventDisableTiming);
        cudaEventCreateWithFlags(&evH,  cudaEventDisableTiming);
        cudaEventCreateWithFlags(&evR2, cudaEventDisableTiming);
    }

    const int lin1Blocks = (N_NODES / 2 * 4 + 255) / 256;      // 391
    const int nodeBlocks = (N_NODES + 127) / 128;
    const int scat1Blocks = (EQ * 4 + 255) / 256;
    const int scat2Blocks = ((int)(3u * EQ) + 255) / 256;

    // Fork side stream from captured stream.
    cudaEventRecord(ev0, 0);
    cudaStreamWaitEvent(s2, ev0, 0);

    k_lin1y<<<lin1Blocks + 1, 256>>>(x, w_rel1, (const int*)ei);   // +1 detect
    k_lin1r<<<lin1Blocks, 256, 0, s2>>>(x, w_root1);
    cudaEventRecord(evR1, s2);

    k_scat1<<<scat1Blocks, 256>>>(ei);

    cudaStreamWaitEvent(0, evR1, 0);           // need r1 (and agg2 zeroed later)
    k_lin2h<<<nodeBlocks, 128>>>(b_rel1, w_rel2);
    cudaEventRecord(evH, 0);
    cudaStreamWaitEvent(s2, evH, 0);
    k_lin2r<<<nodeBlocks, 128, 0, s2>>>(w_root2);
    cudaEventRecord(evR2, s2);

    k_scat2<<<scat2Blocks, 256>>>(ei);

    cudaStreamWaitEvent(0, evR2, 0);
    k_out<<<nodeBlocks, 128>>>(b_rel2, out);
}

// round 8
// speedup vs baseline: 2.4880x; 1.0008x over previous
#include <cuda_runtime.h>
#include <cuda_bf16.h>
#include <math.h>

#define N_NODES  50000
#define N_EDGES  1600000
#define EG       (N_EDGES / 4)
#define IN_CH    64
#define HID      16
#define NCLS     10
#define HID2P    12

// ---------------- device scratch ----------------
__device__ __align__(16) float g_y1  [N_NODES * HID];    // x @ w_rel1
__device__ __align__(16) float g_r1  [N_NODES * HID];    // x @ w_root1
__device__ __align__(16) float g_agg1[N_NODES * HID];    // segment_sum(y1)
__device__ __align__(16) float g_h   [N_NODES * HID];    // relu hidden
__device__ __align__(16) float g_y2  [N_NODES * HID2P];  // h @ w_rel2 (padded)
__device__ __align__(16) float g_r2  [N_NODES * HID2P];  // h @ w_root2
__device__ __align__(16) float g_agg2[N_NODES * HID2P];  // segment_sum(y2)
__device__ int g_is64;                                   // edge dtype flag

// ---------------- kernels ----------------

// y1 = x @ w_rel1, zero agg1, detect edge dtype (last block).
// thread = pair*4 + part; pair = nodes {2p,2p+1}; part = column quarter.
__global__ __launch_bounds__(256) void k_lin1y(const float* __restrict__ x,
                                               const float* __restrict__ w_rel,
                                               const int* __restrict__ ei32) {
    if (blockIdx.x == gridDim.x - 1) {
        __shared__ int s_or;
        if (threadIdx.x == 0) s_or = 0;
        __syncthreads();
        int v = 0;
        for (int i = threadIdx.x; i < 1024; i += 256)
            v |= ei32[2 * i + 1];
        if (v) atomicOr(&s_or, 1);
        __syncthreads();
        if (threadIdx.x == 0) g_is64 = (s_or == 0) ? 1 : 0;
        return;
    }

    __shared__ float sw[IN_CH * HID];
    for (int i = threadIdx.x; i < IN_CH * HID; i += 256) sw[i] = w_rel[i];
    __syncthreads();

    int t = blockIdx.x * 256 + threadIdx.x;
    int pair = t >> 2;
    if (pair >= N_NODES / 2) return;
    int part = t & 3;
    int jbase = part * 4;
    int n0 = pair * 2, n1 = n0 + 1;

    {
        float4 z = make_float4(0.f, 0.f, 0.f, 0.f);
        float4* az = reinterpret_cast<float4*>(g_agg1 + (size_t)pair * 2 * HID);
        az[2 * part] = z;
        az[2 * part + 1] = z;
    }

    float a0[4] = {0.f, 0.f, 0.f, 0.f};
    float a1[4] = {0.f, 0.f, 0.f, 0.f};
    const float4* x0 = reinterpret_cast<const float4*>(x + (size_t)n0 * IN_CH);
    const float4* x1 = reinterpret_cast<const float4*>(x + (size_t)n1 * IN_CH);
#pragma unroll
    for (int k4 = 0; k4 < IN_CH / 4; k4++) {
        float4 v0 = __ldg(x0 + k4);
        float4 v1 = __ldg(x1 + k4);
        float s0[4] = {v0.x, v0.y, v0.z, v0.w};
        float s1[4] = {v1.x, v1.y, v1.z, v1.w};
#pragma unroll
        for (int u = 0; u < 4; u++) {
            const float* wr = sw + (k4 * 4 + u) * HID + jbase;
#pragma unroll
            for (int j = 0; j < 4; j++) {
                float wv = wr[j];
                a0[j] = fmaf(s0[u], wv, a0[j]);
                a1[j] = fmaf(s1[u], wv, a1[j]);
            }
        }
    }
    *reinterpret_cast<float4*>(g_y1 + (size_t)n0 * HID + jbase) =
        make_float4(a0[0], a0[1], a0[2], a0[3]);
    *reinterpret_cast<float4*>(g_y1 + (size_t)n1 * HID + jbase) =
        make_float4(a1[0], a1[1], a1[2], a1[3]);
}

// r1 = x @ w_root1, zero agg2 (side stream).
__global__ __launch_bounds__(256) void k_lin1r(const float* __restrict__ x,
                                               const float* __restrict__ w_root) {
    __shared__ float su[IN_CH * HID];
    for (int i = threadIdx.x; i < IN_CH * HID; i += 256) su[i] = w_root[i];
    __syncthreads();

    int t = blockIdx.x * 256 + threadIdx.x;
    int pair = t >> 2;
    if (pair >= N_NODES / 2) return;
    int part = t & 3;
    int jbase = part * 4;
    int n0 = pair * 2, n1 = n0 + 1;

    {
        float4 z = make_float4(0.f, 0.f, 0.f, 0.f);
        float4* az = reinterpret_cast<float4*>(g_agg2 + (size_t)pair * 2 * HID2P);
        if (part == 0)      { az[0] = z; az[1] = z; }
        else if (part == 1) { az[2] = z; az[3] = z; }
        else if (part == 2) { az[4] = z; }
        else                { az[5] = z; }
    }

    float a0[4] = {0.f, 0.f, 0.f, 0.f};
    float a1[4] = {0.f, 0.f, 0.f, 0.f};
    const float4* x0 = reinterpret_cast<const float4*>(x + (size_t)n0 * IN_CH);
    const float4* x1 = reinterpret_cast<const float4*>(x + (size_t)n1 * IN_CH);
#pragma unroll
    for (int k4 = 0; k4 < IN_CH / 4; k4++) {
        float4 v0 = __ldg(x0 + k4);
        float4 v1 = __ldg(x1 + k4);
        float s0[4] = {v0.x, v0.y, v0.z, v0.w};
        float s1[4] = {v1.x, v1.y, v1.z, v1.w};
#pragma unroll
        for (int u = 0; u < 4; u++) {
            const float* wr = su + (k4 * 4 + u) * HID + jbase;
#pragma unroll
            for (int j = 0; j < 4; j++) {
                float wv = wr[j];
                a0[j] = fmaf(s0[u], wv, a0[j]);
                a1[j] = fmaf(s1[u], wv, a1[j]);
            }
        }
    }
    *reinterpret_cast<float4*>(g_r1 + (size_t)n0 * HID + jbase) =
        make_float4(a0[0], a0[1], a0[2], a0[3]);
    *reinterpret_cast<float4*>(g_r1 + (size_t)n1 * HID + jbase) =
        make_float4(a1[0], a1[1], a1[2], a1[3]);
}

// Layer-1 scatter, ILP=4 consecutive: thread = (eg, quarter), edges eg*4..+3.
// Index loads are one int4 per direction.
__global__ __launch_bounds__(256) void k_scat1(const void* __restrict__ ei) {
    const bool is64 = (g_is64 != 0);
    int t = blockIdx.x * 256 + threadIdx.x;
    int eg = t >> 2;
    if (eg >= EG) return;
    int q = t & 3;
    int s[4], d[4];
    if (is64) {
        const long long* p = (const long long*)ei;
#pragma unroll
        for (int i = 0; i < 4; i++) {
            s[i] = (int)p[eg * 4 + i];
            d[i] = (int)p[N_EDGES + eg * 4 + i];
        }
    } else {
        const int* p = (const int*)ei;
        int4 sv = __ldg(reinterpret_cast<const int4*>(p) + eg);
        int4 dv = __ldg(reinterpret_cast<const int4*>(p + N_EDGES) + eg);
        s[0] = sv.x; s[1] = sv.y; s[2] = sv.z; s[3] = sv.w;
        d[0] = dv.x; d[1] = dv.y; d[2] = dv.z; d[3] = dv.w;
    }
    float4 v[4];
#pragma unroll
    for (int i = 0; i < 4; i++)
        v[i] = __ldg(reinterpret_cast<const float4*>(g_y1 + (size_t)s[i] * HID) + q);
#pragma unroll
    for (int i = 0; i < 4; i++) {
        float* dp = g_agg1 + (size_t)d[i] * HID + q * 4;
        asm volatile("red.global.add.v4.f32 [%0], {%1, %2, %3, %4};"
                     :: "l"(dp), "f"(v[i].x), "f"(v[i].y), "f"(v[i].z), "f"(v[i].w)
                     : "memory");
    }
}

// h = relu(agg1 + b1 + r1) -> g_h ; y2 = h @ w_rel2 (padded to 12)
// thread = node*2 + half; each half computes 5 classes + writes 8 h values.
__global__ __launch_bounds__(256) void k_lin2h(const float* __restrict__ b1,
                                               const float* __restrict__ w_rel2) {
    __shared__ float sw[HID * NCLS];
    __shared__ float sb[HID];
    for (int i = threadIdx.x; i < HID * NCLS; i += 256) sw[i] = w_rel2[i];
    if (threadIdx.x < HID) sb[threadIdx.x] = b1[threadIdx.x];
    __syncthreads();

    int t = blockIdx.x * 256 + threadIdx.x;
    int node = t >> 1;
    if (node >= N_NODES) return;
    int half = t & 1;

    float h[HID];
    const float4* ag = reinterpret_cast<const float4*>(g_agg1 + (size_t)node * HID);
    const float4* rr = reinterpret_cast<const float4*>(g_r1 + (size_t)node * HID);
#pragma unroll
    for (int qd = 0; qd < 4; qd++) {
        float4 a = ag[qd];
        float4 r = rr[qd];
        float v0 = a.x + sb[qd*4+0] + r.x;
        float v1 = a.y + sb[qd*4+1] + r.y;
        float v2 = a.z + sb[qd*4+2] + r.z;
        float v3 = a.w + sb[qd*4+3] + r.w;
        h[qd*4+0] = v0 > 0.f ? v0 : 0.f;
        h[qd*4+1] = v1 > 0.f ? v1 : 0.f;
        h[qd*4+2] = v2 > 0.f ? v2 : 0.f;
        h[qd*4+3] = v3 > 0.f ? v3 : 0.f;
    }
    // Each half writes its 8 h values (2 float4s).
    float4* hd = reinterpret_cast<float4*>(g_h + (size_t)node * HID);
    hd[half*2+0] = make_float4(h[half*8+0], h[half*8+1], h[half*8+2], h[half*8+3]);
    hd[half*2+1] = make_float4(h[half*8+4], h[half*8+5], h[half*8+6], h[half*8+7]);

    int cbase = half * 5;
    float y[5] = {0.f, 0.f, 0.f, 0.f, 0.f};
#pragma unroll
    for (int j = 0; j < HID; j++) {
        const float* wr = sw + j * NCLS + cbase;
#pragma unroll
        for (int c = 0; c < 5; c++)
            y[c] = fmaf(h[j], wr[c], y[c]);
    }
    float* y2 = g_y2 + (size_t)node * HID2P;
#pragma unroll
    for (int c = 0; c < 5; c++) y2[cbase + c] = y[c];
    if (half == 1) { y2[10] = 0.f; y2[11] = 0.f; }
}

// r2 = h @ w_root2 (side stream, overlaps scat2). thread = node*2 + half.
__global__ __launch_bounds__(256) void k_lin2r(const float* __restrict__ w_root2) {
    __shared__ float su[HID * NCLS];
    for (int i = threadIdx.x; i < HID * NCLS; i += 256) su[i] = w_root2[i];
    __syncthreads();

    int t = blockIdx.x * 256 + threadIdx.x;
    int node = t >> 1;
    if (node >= N_NODES) return;
    int half = t & 1;

    float h[HID];
    const float4* hs = reinterpret_cast<const float4*>(g_h + (size_t)node * HID);
#pragma unroll
    for (int qd = 0; qd < 4; qd++) {
        float4 v = hs[qd];
        h[qd*4+0] = v.x; h[qd*4+1] = v.y; h[qd*4+2] = v.z; h[qd*4+3] = v.w;
    }
    int cbase = half * 5;
    float r[5] = {0.f, 0.f, 0.f, 0.f, 0.f};
#pragma unroll
    for (int j = 0; j < HID; j++) {
        const float* wr = su + j * NCLS + cbase;
#pragma unroll
        for (int c = 0; c < 5; c++)
            r[c] = fmaf(h[j], wr[c], r[c]);
    }
    float* r2 = g_r2 + (size_t)node * HID2P;
#pragma unroll
    for (int c = 0; c < 5; c++) r2[cbase + c] = r[c];
}

// Layer-2 scatter, ILP=4 consecutive: thread = (eg, third), edges eg*4..+3.
__global__ __launch_bounds__(256) void k_scat2(const void* __restrict__ ei) {
    const bool is64 = (g_is64 != 0);
    unsigned t = blockIdx.x * 256 + threadIdx.x;
    if (t >= 3u * EG) return;
    unsigned eg = (unsigned)(((unsigned long long)t * 0x55555556ULL) >> 32);  // t/3
    unsigned q = t - eg * 3u;
    int s[4], d[4];
    if (is64) {
        const long long* p = (const long long*)ei;
#pragma unroll
        for (int i = 0; i < 4; i++) {
            s[i] = (int)p[eg * 4 + i];
            d[i] = (int)p[N_EDGES + eg * 4 + i];
        }
    } else {
        const int* p = (const int*)ei;
        int4 sv = __ldg(reinterpret_cast<const int4*>(p) + eg);
        int4 dv = __ldg(reinterpret_cast<const int4*>(p + N_EDGES) + eg);
        s[0] = sv.x; s[1] = sv.y; s[2] = sv.z; s[3] = sv.w;
        d[0] = dv.x; d[1] = dv.y; d[2] = dv.z; d[3] = dv.w;
    }
    float4 v[4];
#pragma unroll
    for (int i = 0; i < 4; i++)
        v[i] = __ldg(reinterpret_cast<const float4*>(g_y2 + (size_t)s[i] * HID2P) + q);
#pragma unroll
    for (int i = 0; i < 4; i++) {
        float* dp = g_agg2 + (size_t)d[i] * HID2P + q * 4;
        asm volatile("red.global.add.v4.f32 [%0], {%1, %2, %3, %4};"
                     :: "l"(dp), "f"(v[i].x), "f"(v[i].y), "f"(v[i].z), "f"(v[i].w)
                     : "memory");
    }
}

// out = log_softmax(agg2 + b2 + r2)
__global__ __launch_bounds__(128) void k_out(const float* __restrict__ b2,
                                             float* __restrict__ out) {
    __shared__ float sb[NCLS];
    if (threadIdx.x < NCLS) sb[threadIdx.x] = b2[threadIdx.x];
    __syncthreads();

    int node = blockIdx.x * 128 + threadIdx.x;
    if (node >= N_NODES) return;

    float o[NCLS];
#pragma unroll
    for (int c = 0; c < NCLS; c++)
        o[c] = g_agg2[(size_t)node * HID2P + c] + sb[c] + g_r2[(size_t)node * HID2P + c];

    float m = o[0];
#pragma unroll
    for (int c = 1; c < NCLS; c++) m = fmaxf(m, o[c]);
    float sum = 0.f;
#pragma unroll
    for (int c = 0; c < NCLS; c++) sum += __expf(o[c] - m);
    float ls = m + logf(sum);
#pragma unroll
    for (int c = 0; c < NCLS; c++)
        out[(size_t)node * NCLS + c] = o[c] - ls;
}

// ---------------- launch ----------------
extern "C" void kernel_launch(void* const* d_in, const int* in_sizes, int n_in,
                              void* d_out, int out_size) {
    const float* x       = (const float*)d_in[0];
    const void*  ei      = d_in[1];
    const float* w_rel1  = (const float*)d_in[2];
    const float* b_rel1  = (const float*)d_in[3];
    const float* w_root1 = (const float*)d_in[4];
    const float* w_rel2  = (const float*)d_in[5];
    const float* b_rel2  = (const float*)d_in[6];
    const float* w_root2 = (const float*)d_in[7];
    float* out = (float*)d_out;

    static cudaStream_t s2 = nullptr;
    static cudaEvent_t ev0, evR1, evH, evR2;
    if (!s2) {
        cudaStreamCreateWithFlags(&s2, cudaStreamNonBlocking);
        cudaEventCreateWithFlags(&ev0,  cudaEventDisableTiming);
        cudaEventCreateWithFlags(&evR1, cudaEventDisableTiming);
        cudaEventCreateWithFlags(&evH,  cudaEventDisableTiming);
        cudaEventCreateWithFlags(&evR2, cudaEventDisableTiming);
    }

    const int lin1Blocks = (N_NODES / 2 * 4 + 255) / 256;      // 391
    const int lin2Blocks = (N_NODES * 2 + 255) / 256;          // 391
    const int nodeBlocks = (N_NODES + 127) / 128;
    const int scat1Blocks = (EG * 4 + 255) / 256;
    const int scat2Blocks = ((int)(3u * EG) + 255) / 256;

    cudaEventRecord(ev0, 0);
    cudaStreamWaitEvent(s2, ev0, 0);

    k_lin1y<<<lin1Blocks + 1, 256>>>(x, w_rel1, (const int*)ei);   // +1 detect
    k_lin1r<<<lin1Blocks, 256, 0, s2>>>(x, w_root1);
    cudaEventRecord(evR1, s2);

    k_scat1<<<scat1Blocks, 256>>>(ei);

    cudaStreamWaitEvent(0, evR1, 0);
    k_lin2h<<<lin2Blocks, 256>>>(b_rel1, w_rel2);
    cudaEventRecord(evH, 0);
    cudaStreamWaitEvent(s2, evH, 0);
    k_lin2r<<<lin2Blocks, 256, 0, s2>>>(w_root2);
    cudaEventRecord(evR2, s2);

    k_scat2<<<scat2Blocks, 256>>>(ei);

    cudaStreamWaitEvent(0, evR2, 0);
    k_out<<<nodeBlocks, 128>>>(b_rel2, out);
}